// round 2
// baseline (speedup 1.0000x reference)
#include <cuda_runtime.h>

#define NB 8
#define NS 4096
#define NH 8
#define ND 128
#define ROW (NH * ND)                 // 1024 floats per token-row
#define VPR (ROW / 4)                 // 256 float4 per row
#define MAX_TOTAL (NB * NS)           // 32768 rows per cache
#define CACHE_F (MAX_TOTAL * ROW)     // floats per cache
#define CACHE_V (MAX_TOTAL * VPR)     // 8388608 float4 per cache
#define TOTAL_V (2 * CACHE_V)         // 16777216 float4
#define F4_PER_THREAD 4
#define THREADS 256
#define BLOCKS (TOTAL_V / (THREADS * F4_PER_THREAD))   // 16384

// Single fused kernel: every block computes the 9-entry cumsum from seq_lens
// (32B, L2-resident), then streams 4 consecutive float4 per thread.
// Block 0 additionally writes the scalar tail outputs (seq_lens, cumsum as floats).
__global__ void __launch_bounds__(THREADS) pack_kernel(
    const float4* __restrict__ k_src,
    const float4* __restrict__ v_src,
    const int* __restrict__ seq_lens,
    float4* __restrict__ out)
{
    __shared__ int cs[NB + 1];
    if (threadIdx.x == 0) {
        int c = 0;
        cs[0] = 0;
        #pragma unroll
        for (int i = 0; i < NB; i++) { c += seq_lens[i]; cs[i + 1] = c; }
    }
    __syncthreads();

    if (blockIdx.x == 0 && threadIdx.x == 0) {
        float* seq_out = (float*)out + 2 * (long long)CACHE_F;  // [NB]
        float* cum_out = seq_out + NB;                           // [NB+1]
        #pragma unroll
        for (int i = 0; i < NB; i++) seq_out[i] = (float)(cs[i + 1] - cs[i]);
        #pragma unroll
        for (int i = 0; i <= NB; i++) cum_out[i] = (float)cs[i];
    }

    // Base float4 index for this thread; 4 consecutive float4 (64B) per thread.
    // 4 | 256 (VPR), so all 4 elements lie in the SAME token-row.
    int idx = (blockIdx.x * THREADS + threadIdx.x) * F4_PER_THREAD;

    int which = (idx >= CACHE_V) ? 1 : 0;        // 0 = K cache, 1 = V cache
    int j = idx - which * CACHE_V;
    int row = j >> 8;                             // j / VPR
    int c   = j & (VPR - 1);                      // j % VPR

    float4 v0, v1, v2, v3;
    int total = cs[NB];
    if (row < total) {
        int b = 0;
        #pragma unroll
        for (int bb = 1; bb < NB; bb++)
            if (row >= cs[bb]) b = bb;
        int t = row - cs[b];
        const float4* src = (which ? v_src : k_src) + (long long)(b * NS + t) * VPR + c;
        // front-batched: 4 independent LDG.128 in flight
        v0 = src[0]; v1 = src[1]; v2 = src[2]; v3 = src[3];
    } else {
        v0 = v1 = v2 = v3 = make_float4(0.f, 0.f, 0.f, 0.f);
    }

    float4* dst = out + idx;
    dst[0] = v0; dst[1] = v1; dst[2] = v2; dst[3] = v3;
}

extern "C" void kernel_launch(void* const* d_in, const int* in_sizes, int n_in,
                              void* d_out, int out_size) {
    const float4* key_states   = (const float4*)d_in[0];
    const float4* value_states = (const float4*)d_in[1];
    const int*    seq_lens     = (const int*)d_in[2];

    pack_kernel<<<BLOCKS, THREADS>>>(key_states, value_states, seq_lens,
                                     (float4*)d_out);
}

// round 3
// speedup vs baseline: 1.2188x; 1.2188x over previous
#include <cuda_runtime.h>

#define NB 8
#define NS 4096
#define NH 8
#define ND 128
#define ROW (NH * ND)                 // 1024 floats per token-row
#define VPR (ROW / 4)                 // 256 float4 per row
#define MAX_TOTAL (NB * NS)           // 32768 rows per cache
#define CACHE_F (MAX_TOTAL * ROW)     // floats per cache
#define CACHE_V (MAX_TOTAL * VPR)     // 8388608 float4 per cache
#define TOTAL_V (2 * CACHE_V)         // 16777216 float4
#define THREADS 256
#define F4_PER_WARP 128               // 4 float4 per thread, warp-interleaved
#define WARPS_PER_BLOCK (THREADS / 32)
#define BLOCKS (TOTAL_V / (F4_PER_WARP * WARPS_PER_BLOCK))   // 16384

// Fused single kernel. Each warp owns 128 consecutive float4 (2KB), aligned to
// a half token-row, so all 4 elements of a thread share one (batch,token) row.
// Lane l handles base + {0,32,64,96} + l -> every LDG/STG fully coalesced,
// 4 independent loads in flight per thread.
__global__ void __launch_bounds__(THREADS) pack_kernel(
    const float4* __restrict__ k_src,
    const float4* __restrict__ v_src,
    const int* __restrict__ seq_lens,
    float4* __restrict__ out)
{
    __shared__ int cs[NB + 1];
    if (threadIdx.x == 0) {
        int c = 0;
        cs[0] = 0;
        #pragma unroll
        for (int i = 0; i < NB; i++) { c += __ldg(seq_lens + i); cs[i + 1] = c; }
    }
    __syncthreads();

    if (blockIdx.x == 0 && threadIdx.x == 0) {
        float* seq_out = (float*)out + 2 * (long long)CACHE_F;  // [NB]
        float* cum_out = seq_out + NB;                           // [NB+1]
        #pragma unroll
        for (int i = 0; i < NB; i++) seq_out[i] = (float)(cs[i + 1] - cs[i]);
        #pragma unroll
        for (int i = 0; i <= NB; i++) cum_out[i] = (float)cs[i];
    }

    int lane = threadIdx.x & 31;
    int gw   = blockIdx.x * WARPS_PER_BLOCK + (threadIdx.x >> 5);
    int base = gw * F4_PER_WARP;                  // warp's first float4 index

    int which = (base >= CACHE_V) ? 1 : 0;        // whole warp in one cache (128 | CACHE_V)
    int j   = base - which * CACHE_V;
    int row = j >> 8;                              // token-row (same for all 4 elems)
    int col = (j & (VPR - 1)) + lane;              // 0 or 128, plus lane

    float4 v0, v1, v2, v3;
    if (row < cs[NB]) {
        int b = 0;
        #pragma unroll
        for (int bb = 1; bb < NB; bb++)
            if (row >= cs[bb]) b = bb;
        int t = row - cs[b];
        const float4* src = (which ? v_src : k_src)
                          + (long long)(b * NS + t) * VPR + col;
        v0 = src[0]; v1 = src[32]; v2 = src[64]; v3 = src[96];
    } else {
        v0 = v1 = v2 = v3 = make_float4(0.f, 0.f, 0.f, 0.f);
    }

    float4* dst = out + base + lane;
    dst[0]  = v0;
    dst[32] = v1;
    dst[64] = v2;
    dst[96] = v3;
}

extern "C" void kernel_launch(void* const* d_in, const int* in_sizes, int n_in,
                              void* d_out, int out_size) {
    const float4* key_states   = (const float4*)d_in[0];
    const float4* value_states = (const float4*)d_in[1];
    const int*    seq_lens     = (const int*)d_in[2];

    pack_kernel<<<BLOCKS, THREADS>>>(key_states, value_states, seq_lens,
                                     (float4*)d_out);
}